// round 13
// baseline (speedup 1.0000x reference)
#include <cuda_runtime.h>
#include <cuda_fp16.h>
#include <cstdint>

static constexpr int NTOK = 32768;   // 8 * 4096
static constexpr int DIM  = 512;
static constexpr int HID  = 2048;
static constexpr int NEXP = 8;
static constexpr int MAXE = 2 * NTOK;

// GEMM tiling: block 128x256x32(halves), 8 warps (2m x 4n), warp tile 64x64, mma m16n8k16 f16
static constexpr int BM = 128, BN = 256, BKH = 32;       // BKH halves per chunk = 64 B/row
static constexpr int A_BYTES = BM * 64;                  // 8192
static constexpr int B_BYTES = BN * 64;                  // 16384
static constexpr int STAGE_BYTES = A_BYTES + B_BYTES;    // 24576
static constexpr int STAGES = 3;
static constexpr int SMEM_BYTES = STAGES * STAGE_BYTES;  // 73728 (also >= 128*132*4 epilogue stage)

static constexpr int MBLK = MAXE / BM;                   // 512 m-blocks per expert (max)
static constexpr int NG1 = NEXP * MBLK * (HID / BN);     // 32768 G1 tiles
static constexpr int NG2 = NEXP * MBLK * (DIM / BN);     // 8192  G2 tiles

// ---------------- scratch ----------------
__device__ int   g_counts[NEXP];
__device__ int   g_offsets[NEXP + 1];
__device__ int   g_cursors[NEXP];
__device__ int   g_ready[NEXP * MBLK];
__device__ int   g_tok[MAXE];
__device__ float g_w[MAXE];
__device__ int   g_cnt[NTOK];
__device__ int   g_pos[2 * NTOK];
__device__ __align__(16) __half g_xh[(long long)NTOK * DIM];         // 32 MB  packed fp16 x
__device__ __align__(16) __half g_W1h[(long long)NEXP * HID * DIM];  // 16 MB  [e][n][k-packed]
__device__ __align__(16) __half g_W2h[(long long)NEXP * DIM * HID];  // 16 MB  [e][n][k-packed]
__device__ __align__(16) __half g_h[(long long)MAXE * HID];          // 256 MB packed fp16 hidden
__device__ __align__(16) float  g_y[(long long)MAXE * DIM];          // 128 MB per-entry output

// ---------------- helpers ----------------
__device__ __forceinline__ uint32_t smem_u32(const void* p) {
    uint32_t a;
    asm("{ .reg .u64 t; cvta.to.shared.u64 t, %1; cvt.u32.u64 %0, t; }" : "=r"(a) : "l"(p));
    return a;
}
__device__ __forceinline__ void cp16(uint32_t daddr, const void* gptr) {
    asm volatile("cp.async.cg.shared.global [%0], [%1], 16;" :: "r"(daddr), "l"(gptr) : "memory");
}
__device__ __forceinline__ uint32_t h2u(__half2 h) { return *(uint32_t*)&h; }

__device__ __forceinline__ void mma16816(float* c, uint32_t a0, uint32_t a1, uint32_t a2, uint32_t a3,
                                         uint32_t b0, uint32_t b1) {
    asm volatile(
        "mma.sync.aligned.m16n8k16.row.col.f32.f16.f16.f32 "
        "{%0,%1,%2,%3}, {%4,%5,%6,%7}, {%8,%9}, {%0,%1,%2,%3};"
        : "+f"(c[0]), "+f"(c[1]), "+f"(c[2]), "+f"(c[3])
        : "r"(a0), "r"(a1), "r"(a2), "r"(a3), "r"(b0), "r"(b1));
}

// ---------------- routing (block-aggregated atomics) ----------------
__global__ void k_count(const int* __restrict__ assign) {
    __shared__ int sc[NEXP];
    int tid = threadIdx.x;
    if (tid < NEXP) sc[tid] = 0;
    __syncthreads();
    int t = blockIdx.x * blockDim.x + tid;
    if (t < NEXP * MBLK) g_ready[t] = 0;     // zero readiness flags (4096 < 32768 threads)
    if (t < NTOK) {
        int a0 = assign[2 * t], a1 = assign[2 * t + 1];
        atomicAdd(&sc[a0], 1);
        if (a1 != a0) atomicAdd(&sc[a1], 1);
    }
    __syncthreads();
    if (tid < NEXP && sc[tid] > 0) atomicAdd(&g_counts[tid], sc[tid]);
}
__global__ void k_scan() {
    int off = 0;
    for (int e = 0; e < NEXP; e++) {
        g_offsets[e] = off;
        g_cursors[e] = off;
        off += g_counts[e];
    }
    g_offsets[NEXP] = off;
}
__global__ void k_place(const int* __restrict__ assign) {
    __shared__ int sc[NEXP];     // block count
    __shared__ int sbase[NEXP];  // reserved global base
    __shared__ int slc[NEXP];    // block-local cursor
    int tid = threadIdx.x;
    if (tid < NEXP) { sc[tid] = 0; slc[tid] = 0; }
    __syncthreads();
    int t = blockIdx.x * blockDim.x + tid;
    int a0 = 0, a1 = 0;
    bool ok = t < NTOK;
    if (ok) {
        a0 = assign[2 * t]; a1 = assign[2 * t + 1];
        atomicAdd(&sc[a0], 1);
        if (a1 != a0) atomicAdd(&sc[a1], 1);
    }
    __syncthreads();
    if (tid < NEXP) sbase[tid] = (sc[tid] > 0) ? atomicAdd(&g_cursors[tid], sc[tid]) : 0;
    __syncthreads();
    if (ok) {
        if (a0 == a1) {
            int p = sbase[a0] + atomicAdd(&slc[a0], 1);
            g_tok[p] = t; g_w[p] = 1.0f;
            g_pos[2 * t] = p; g_cnt[t] = 1;
        } else {
            int p = sbase[a0] + atomicAdd(&slc[a0], 1);
            g_tok[p] = t; g_w[p] = 0.5f;
            int q = sbase[a1] + atomicAdd(&slc[a1], 1);
            g_tok[q] = t; g_w[q] = 0.5f;
            g_pos[2 * t] = p; g_pos[2 * t + 1] = q; g_cnt[t] = 2;
        }
    }
}

// ---------------- pre-pack: x fp32 -> fp16 k-packed (+ zero counts) ----------------
__global__ void k_pack_x(const float* __restrict__ x) {
    if (blockIdx.x == 0 && threadIdx.x < NEXP) g_counts[threadIdx.x] = 0;
    int t = blockIdx.x;
    int q = threadIdx.x;                 // output u32 index within row, 256 = DIM/2
    int group = q >> 4, p = q & 15;
    int o = (p & 3) * 4 + (p >> 2);      // inverse of p = 4*(o%4)+o/4
    int col = group * 32 + 2 * o;
    float2 v = *(const float2*)(x + (long long)t * DIM + col);
    ((uint32_t*)g_xh)[(long long)t * (DIM / 2) + q] = h2u(__floats2half2_rn(v.x, v.y));
}

// ---------------- pre-pack: W1 & W2 [e][K][N] -> [e][n][k-packed] fp16, one launch ----------------
__global__ void k_pack_w(const float* __restrict__ W1, const float* __restrict__ W2) {
    __shared__ float tile[32][33];
    bool isW1 = blockIdx.z < 8;
    int e = isW1 ? blockIdx.z : blockIdx.z - 8;
    int K = isW1 ? DIM : HID;
    int N = isW1 ? HID : DIM;
    const float* src = (isW1 ? W1 : W2) + (long long)e * K * N;
    uint32_t* dst = (uint32_t*)((isW1 ? g_W1h : g_W2h) + (long long)e * (long long)N * K);
    int n0 = (isW1 ? blockIdx.x : blockIdx.y) * 32;
    int k0 = (isW1 ? blockIdx.y : blockIdx.x) * 32;
    int tx = threadIdx.x, ty = threadIdx.y;
    #pragma unroll
    for (int i = ty; i < 32; i += 8)
        tile[i][tx] = src[(long long)(k0 + i) * N + n0 + tx];
    __syncthreads();
    int tid = ty * 32 + tx;
    #pragma unroll
    for (int it = 0; it < 2; it++) {
        int j = tid + it * 256;          // 512 output u32 per tile
        int i = j >> 4, q = j & 15;      // n-row, u32-in-chunk
        int o = (q & 3) * 4 + (q >> 2);
        __half2 h = __floats2half2_rn(tile[2 * o][i], tile[2 * o + 1][i]);
        dst[(long long)(n0 + i) * (K / 2) + (k0 >> 1) + q] = h2u(h);
    }
}

// ---------------- fp16 mma.sync GEMM body (R8 structure, unchanged) ----------------
template <int KTOT, bool G1>
__device__ __forceinline__ void gemm_body(char* smem, int e, int m0, int seg1, int n0,
                                          const float* __restrict__ bias, int rid)
{
    constexpr int NTOT = G1 ? HID : DIM;
    constexpr int CH = KTOT / BKH;

    const __half* Asrc = G1 ? (const __half*)g_xh : (const __half*)g_h;
    const __half* W    = G1 ? (const __half*)g_W1h : (const __half*)g_W2h;

    int tid = threadIdx.x;
    int lane = tid & 31, wid = tid >> 5;
    int warp_m = wid & 1, warp_n = wid >> 1;

    // ---- cp.async mapping: pieces of 16B; row stride 64B; XOR-16B swizzle by row&3 ----
    int pr = tid >> 2;                   // base row 0..63
    int pc = tid & 3;                    // 16B piece in row
    uint32_t swz = (uint32_t)((pc ^ (pr & 3)) * 16);
    uint32_t sbase = smem_u32(smem);

    const __half* aP[2];
    uint32_t aD[2];
    #pragma unroll
    for (int i = 0; i < 2; i++) {
        int r = pr + i * 64;
        int gm = min(m0 + r, seg1 - 1);
        long long srow = G1 ? (long long)g_tok[gm] : (long long)gm;
        aP[i] = Asrc + srow * KTOT + pc * 8;
        aD[i] = sbase + (uint32_t)r * 64u + swz;
    }
    const __half* bP[4];
    uint32_t bD[4];
    #pragma unroll
    for (int k = 0; k < 4; k++) {
        int r = pr + k * 64;
        bP[k] = W + ((long long)e * NTOT + (n0 + r)) * (long long)KTOT + pc * 8;
        bD[k] = sbase + (uint32_t)A_BYTES + (uint32_t)r * 64u + swz;
    }

    auto load_chunk = [&](int c, int s) {
        uint32_t so = (uint32_t)(s * STAGE_BYTES);
        cp16(aD[0] + so, aP[0] + c * BKH);
        cp16(aD[1] + so, aP[1] + c * BKH);
        #pragma unroll
        for (int k = 0; k < 4; k++) cp16(bD[k] + so, bP[k] + c * BKH);
        asm volatile("cp.async.commit_group;" ::: "memory");
    };

    float acc[4][8][4];
    #pragma unroll
    for (int mi = 0; mi < 4; mi++)
        #pragma unroll
        for (int nj = 0; nj < 8; nj++)
            #pragma unroll
            for (int q = 0; q < 4; q++) acc[mi][nj][q] = 0.0f;

    load_chunk(0, 0);
    load_chunk(1, 1);

    // fragment byte offsets: row&3 == (lane>>2)&3 for all rows a warp touches
    uint32_t fswz = (uint32_t)(((lane & 3) ^ ((lane >> 2) & 3)) * 16);
    uint32_t aOff = (uint32_t)((warp_m * 64 + (lane >> 2)) * 64) + fswz;
    uint32_t bOff = (uint32_t)A_BYTES + (uint32_t)((warp_n * 64 + (lane >> 2)) * 64) + fswz;

    for (int c = 0; c < CH; c++) {
        int s = c % STAGES;
        if (c + 1 < CH) asm volatile("cp.async.wait_group 1;" ::: "memory");
        else            asm volatile("cp.async.wait_group 0;" ::: "memory");
        __syncthreads();

        const char* st = smem + s * STAGE_BYTES;

        uint4 aR[8];
        #pragma unroll
        for (int mi = 0; mi < 4; mi++) {
            aR[mi * 2 + 0] = *(const uint4*)(st + aOff + mi * 1024);
            aR[mi * 2 + 1] = *(const uint4*)(st + aOff + mi * 1024 + 512);
        }
        #pragma unroll
        for (int nj = 0; nj < 8; nj++) {
            uint4 b = *(const uint4*)(st + bOff + nj * 512);
            #pragma unroll
            for (int mi = 0; mi < 4; mi++) {
                mma16816(acc[mi][nj],
                         aR[mi * 2].x, aR[mi * 2 + 1].x, aR[mi * 2].y, aR[mi * 2 + 1].y,
                         b.x, b.y);
                mma16816(acc[mi][nj],
                         aR[mi * 2].z, aR[mi * 2 + 1].z, aR[mi * 2].w, aR[mi * 2 + 1].w,
                         b.z, b.w);
            }
        }

        __syncthreads();
        if (c + 2 < CH) load_chunk(c + 2, (c + 2) % STAGES);
    }

    // ---- epilogue ----
    const float* bias_e = bias + (long long)e * NTOT;
    float2 bv[8];
    #pragma unroll
    for (int nj = 0; nj < 8; nj++) {
        int col = n0 + warp_n * 64 + nj * 8 + (lane & 3) * 2;
        bv[nj] = *(const float2*)(bias_e + col);
    }

    if (G1) {
        // stage packed half2 into smem (ring is dead now), then coalesced uint4 copy to g_h
        uint32_t* stg = (uint32_t*)smem;   // [128][132] u32
        #pragma unroll
        for (int mi = 0; mi < 4; mi++) {
            int r0 = warp_m * 64 + mi * 16 + (lane >> 2);   // block-relative row
            #pragma unroll
            for (int nj = 0; nj < 8; nj++) {
                int pos = (warp_n * 2 + (nj >> 2)) * 16 + 4 * (lane & 3) + (nj & 3);
                __half2 h0 = __floats2half2_rn(fmaxf(acc[mi][nj][0] + bv[nj].x, 0.0f),
                                               fmaxf(acc[mi][nj][1] + bv[nj].y, 0.0f));
                __half2 h1 = __floats2half2_rn(fmaxf(acc[mi][nj][2] + bv[nj].x, 0.0f),
                                               fmaxf(acc[mi][nj][3] + bv[nj].y, 0.0f));
                stg[r0 * 132 + pos]       = h2u(h0);
                stg[(r0 + 8) * 132 + pos] = h2u(h1);
            }
        }
        __syncthreads();
        uint32_t* gh = (uint32_t*)g_h;
        #pragma unroll
        for (int it = 0; it < 16; it++) {
            int j = tid + it * 256;            // 4096 uint4 total
            int row = j >> 5, q = j & 31;      // 128 rows x 32 uint4
            if (m0 + row < seg1) {
                uint4 v = *(const uint4*)(stg + row * 132 + q * 4);
                *(uint4*)(gh + (long long)(m0 + row) * (HID / 2) + (n0 >> 1) + q * 4) = v;
            }
        }
        // publish readiness for this (e, m-block)
        __threadfence();
        __syncthreads();
        if (tid == 0) atomicAdd(&g_ready[rid], 1);
    } else {
        #pragma unroll
        for (int mi = 0; mi < 4; mi++) {
            int r0 = m0 + warp_m * 64 + mi * 16 + (lane >> 2);
            int r1 = r0 + 8;
            bool ok0 = r0 < seg1, ok1 = r1 < seg1;
            float w0 = ok0 ? g_w[r0] : 0.0f;
            float w1 = ok1 ? g_w[r1] : 0.0f;
            float* d0 = g_y + (long long)r0 * DIM;
            float* d1 = g_y + (long long)r1 * DIM;
            #pragma unroll
            for (int nj = 0; nj < 8; nj++) {
                int col = n0 + warp_n * 64 + nj * 8 + (lane & 3) * 2;
                float2 v0, v1;
                v0.x = (acc[mi][nj][0] + bv[nj].x) * w0;
                v0.y = (acc[mi][nj][1] + bv[nj].y) * w0;
                v1.x = (acc[mi][nj][2] + bv[nj].x) * w1;
                v1.y = (acc[mi][nj][3] + bv[nj].y) * w1;
                if (ok0) *(float2*)(d0 + col) = v0;
                if (ok1) *(float2*)(d1 + col) = v1;
            }
        }
    }
}

// ---------------- fused GEMM1+GEMM2 launch ----------------
// 1-D grid: [0, NG1) = G1 tiles (dispatched first), [NG1, NG1+NG2) = G2 tiles.
// G2 tile (e, mb) spins until its 8 G1 producers have published g_h for m-block mb.
__global__ void __launch_bounds__(256) k_gemm(const float* __restrict__ b1,
                                              const float* __restrict__ b2)
{
    extern __shared__ __align__(16) char smem[];
    int idx = blockIdx.x;

    if (idx < NG1) {
        int e = idx >> 12;                 // 4096 tiles per expert = 512 mb * 8 n
        int rem = idx & 4095;
        int mb = rem >> 3;
        int n0 = (rem & 7) * BN;
        int seg0 = g_offsets[e], seg1 = g_offsets[e + 1];
        int m0 = seg0 + mb * BM;
        if (m0 >= seg1) return;
        gemm_body<DIM, true>(smem, e, m0, seg1, n0, b1, e * MBLK + mb);
    } else {
        int j = idx - NG1;
        int e = j >> 10;                   // 1024 tiles per expert = 512 mb * 2 n
        int rem = j & 1023;
        int mb = rem >> 1;
        int n0 = (rem & 1) * BN;
        int seg0 = g_offsets[e], seg1 = g_offsets[e + 1];
        int m0 = seg0 + mb * BM;
        if (m0 >= seg1) return;
        int rid = e * MBLK + mb;
        if (threadIdx.x == 0) {
            while (atomicAdd(&g_ready[rid], 0) < 8) __nanosleep(128);
        }
        __syncthreads();
        gemm_body<HID, false>(smem, e, m0, seg1, n0, b2, rid);
    }
}

// ---------------- per-token gather ----------------
__global__ void k_gather(float* __restrict__ out) {
    int t = blockIdx.x;
    int c = threadIdx.x;   // 128 threads * float4 = 512 floats
    int cnt = g_cnt[t];
    int p0 = g_pos[2 * t];
    float4 v = ((const float4*)(g_y + (long long)p0 * DIM))[c];
    if (cnt == 2) {
        int p1 = g_pos[2 * t + 1];
        float4 u = ((const float4*)(g_y + (long long)p1 * DIM))[c];
        v.x += u.x; v.y += u.y; v.z += u.z; v.w += u.w;
    }
    ((float4*)(out + (long long)t * DIM))[c] = v;
}

// ---------------- launch ----------------
extern "C" void kernel_launch(void* const* d_in, const int* in_sizes, int n_in,
                              void* d_out, int out_size)
{
    const float* x      = (const float*)d_in[0];
    const int*   assign = (const int*)d_in[1];
    const float* W1     = (const float*)d_in[2];
    const float* b1     = (const float*)d_in[3];
    const float* W2     = (const float*)d_in[4];
    const float* b2     = (const float*)d_in[5];
    float* out = (float*)d_out;

    cudaFuncSetAttribute(k_gemm, cudaFuncAttributeMaxDynamicSharedMemorySize, SMEM_BYTES);

    // pre-pack to fp16, k-fragment packed; W transposed to [n][k]; zeroes g_counts
    k_pack_x<<<NTOK, 256>>>(x);
    k_pack_w<<<dim3(64, 16, 16), dim3(32, 8)>>>(W1, W2);

    // routing (block-aggregated atomics); k_count also zeroes g_ready
    k_count<<<NTOK / 256, 256>>>(assign);
    k_scan<<<1, 1>>>();
    k_place<<<NTOK / 256, 256>>>(assign);

    // fused GEMM1 -> GEMM2 (readiness-flag pipelined)
    k_gemm<<<NG1 + NG2, 256, SMEM_BYTES>>>(b1, b2);

    k_gather<<<NTOK, 128>>>(out);
}

// round 15
// speedup vs baseline: 1.0574x; 1.0574x over previous
#include <cuda_runtime.h>
#include <cuda_fp16.h>
#include <cstdint>

static constexpr int NTOK = 32768;   // 8 * 4096
static constexpr int DIM  = 512;
static constexpr int HID  = 2048;
static constexpr int NEXP = 8;
static constexpr int MAXE = 2 * NTOK;

// GEMM tiling: block 128x256x32(halves), 8 warps (2m x 4n), warp tile 64x64, mma m16n8k16 f16
static constexpr int BM = 128, BN = 256, BKH = 32;       // BKH halves per chunk = 64 B/row
static constexpr int A_BYTES = BM * 64;                  // 8192
static constexpr int B_BYTES = BN * 64;                  // 16384
static constexpr int STAGE_BYTES = A_BYTES + B_BYTES;    // 24576
static constexpr int STAGES = 4;                         // 4 stages -> single barrier per chunk
static constexpr int SMEM_BYTES = STAGES * STAGE_BYTES;  // 98304 (>= 128*132*4 epilogue stage)

// ---------------- scratch ----------------
__device__ int   g_counts[NEXP];
__device__ int   g_offsets[NEXP + 1];
__device__ int   g_cursors[NEXP];
__device__ int   g_done;             // last-block ticket for fused scan
__device__ int   g_tok[MAXE];
__device__ float g_w[MAXE];
__device__ int   g_cnt[NTOK];
__device__ int   g_pos[2 * NTOK];
__device__ __align__(16) __half g_xh[(long long)NTOK * DIM];         // 32 MB  packed fp16 x
__device__ __align__(16) __half g_W1h[(long long)NEXP * HID * DIM];  // 16 MB  [e][n][k-packed]
__device__ __align__(16) __half g_W2h[(long long)NEXP * DIM * HID];  // 16 MB  [e][n][k-packed]
__device__ __align__(16) __half g_h[(long long)MAXE * HID];          // 256 MB packed fp16 hidden
__device__ __align__(16) float  g_y[(long long)MAXE * DIM];          // 128 MB per-entry output

// ---------------- helpers ----------------
__device__ __forceinline__ uint32_t smem_u32(const void* p) {
    uint32_t a;
    asm("{ .reg .u64 t; cvta.to.shared.u64 t, %1; cvt.u32.u64 %0, t; }" : "=r"(a) : "l"(p));
    return a;
}
__device__ __forceinline__ void cp16(uint32_t daddr, const void* gptr) {
    asm volatile("cp.async.cg.shared.global [%0], [%1], 16;" :: "r"(daddr), "l"(gptr) : "memory");
}
__device__ __forceinline__ uint32_t h2u(__half2 h) { return *(uint32_t*)&h; }

__device__ __forceinline__ void mma16816(float* c, uint32_t a0, uint32_t a1, uint32_t a2, uint32_t a3,
                                         uint32_t b0, uint32_t b1) {
    asm volatile(
        "mma.sync.aligned.m16n8k16.row.col.f32.f16.f16.f32 "
        "{%0,%1,%2,%3}, {%4,%5,%6,%7}, {%8,%9}, {%0,%1,%2,%3};"
        : "+f"(c[0]), "+f"(c[1]), "+f"(c[2]), "+f"(c[3])
        : "r"(a0), "r"(a1), "r"(a2), "r"(a3), "r"(b0), "r"(b1));
}

// ---------------- routing (block-aggregated atomics; scan fused via last-block ticket) ----------------
__global__ void k_count(const int* __restrict__ assign) {
    __shared__ int sc[NEXP];
    int tid = threadIdx.x;
    if (tid < NEXP) sc[tid] = 0;
    __syncthreads();
    int t = blockIdx.x * blockDim.x + tid;
    if (t < NTOK) {
        int a0 = assign[2 * t], a1 = assign[2 * t + 1];
        atomicAdd(&sc[a0], 1);
        if (a1 != a0) atomicAdd(&sc[a1], 1);
    }
    __syncthreads();
    if (tid < NEXP && sc[tid] > 0) atomicAdd(&g_counts[tid], sc[tid]);
    // last finishing block performs the 8-entry scan
    if (tid == 0) {
        __threadfence();
        int d = atomicAdd(&g_done, 1);
        if (d == gridDim.x - 1) {
            int off = 0;
            for (int e = 0; e < NEXP; e++) {
                g_offsets[e] = off;
                g_cursors[e] = off;
                off += g_counts[e];
            }
            g_offsets[NEXP] = off;
            g_done = 0;                  // reset for graph replay
            __threadfence();
        }
    }
}
__global__ void k_place(const int* __restrict__ assign) {
    __shared__ int sc[NEXP];     // block count
    __shared__ int sbase[NEXP];  // reserved global base
    __shared__ int slc[NEXP];    // block-local cursor
    int tid = threadIdx.x;
    if (tid < NEXP) { sc[tid] = 0; slc[tid] = 0; }
    __syncthreads();
    int t = blockIdx.x * blockDim.x + tid;
    int a0 = 0, a1 = 0;
    bool ok = t < NTOK;
    if (ok) {
        a0 = assign[2 * t]; a1 = assign[2 * t + 1];
        atomicAdd(&sc[a0], 1);
        if (a1 != a0) atomicAdd(&sc[a1], 1);
    }
    __syncthreads();
    if (tid < NEXP) sbase[tid] = (sc[tid] > 0) ? atomicAdd(&g_cursors[tid], sc[tid]) : 0;
    __syncthreads();
    if (ok) {
        if (a0 == a1) {
            int p = sbase[a0] + atomicAdd(&slc[a0], 1);
            g_tok[p] = t; g_w[p] = 1.0f;
            g_pos[2 * t] = p; g_cnt[t] = 1;
        } else {
            int p = sbase[a0] + atomicAdd(&slc[a0], 1);
            g_tok[p] = t; g_w[p] = 0.5f;
            int q = sbase[a1] + atomicAdd(&slc[a1], 1);
            g_tok[q] = t; g_w[q] = 0.5f;
            g_pos[2 * t] = p; g_pos[2 * t + 1] = q; g_cnt[t] = 2;
        }
    }
}

// ---------------- pre-pack: x fp32 -> fp16 k-packed (+ zero counts) ----------------
__global__ void k_pack_x(const float* __restrict__ x) {
    if (blockIdx.x == 0 && threadIdx.x < NEXP) g_counts[threadIdx.x] = 0;
    int t = blockIdx.x;
    int q = threadIdx.x;                 // output u32 index within row, 256 = DIM/2
    int group = q >> 4, p = q & 15;
    int o = (p & 3) * 4 + (p >> 2);      // inverse of p = 4*(o%4)+o/4
    int col = group * 32 + 2 * o;
    float2 v = *(const float2*)(x + (long long)t * DIM + col);
    ((uint32_t*)g_xh)[(long long)t * (DIM / 2) + q] = h2u(__floats2half2_rn(v.x, v.y));
}

// ---------------- pre-pack: W1 & W2 [e][K][N] -> [e][n][k-packed] fp16, one launch ----------------
// grid (64, 16, 16): z<8 -> W1 (K=512, N=2048: n-tiles on x, k-tiles on y)
//                    z>=8 -> W2 (K=2048, N=512: k-tiles on x, n-tiles on y)
__global__ void k_pack_w(const float* __restrict__ W1, const float* __restrict__ W2) {
    __shared__ float tile[32][33];
    bool isW1 = blockIdx.z < 8;
    int e = isW1 ? blockIdx.z : blockIdx.z - 8;
    int K = isW1 ? DIM : HID;
    int N = isW1 ? HID : DIM;
    const float* src = (isW1 ? W1 : W2) + (long long)e * K * N;
    uint32_t* dst = (uint32_t*)((isW1 ? g_W1h : g_W2h) + (long long)e * (long long)N * K);
    int n0 = (isW1 ? blockIdx.x : blockIdx.y) * 32;
    int k0 = (isW1 ? blockIdx.y : blockIdx.x) * 32;
    int tx = threadIdx.x, ty = threadIdx.y;
    #pragma unroll
    for (int i = ty; i < 32; i += 8)
        tile[i][tx] = src[(long long)(k0 + i) * N + n0 + tx];
    __syncthreads();
    int tid = ty * 32 + tx;
    #pragma unroll
    for (int it = 0; it < 2; it++) {
        int j = tid + it * 256;          // 512 output u32 per tile
        int i = j >> 4, q = j & 15;      // n-row, u32-in-chunk
        int o = (q & 3) * 4 + (q >> 2);
        __half2 h = __floats2half2_rn(tile[2 * o][i], tile[2 * o + 1][i]);
        dst[(long long)(n0 + i) * (K / 2) + (k0 >> 1) + q] = h2u(h);
    }
}

// ---------------- fp16 mma.sync GEMM (4-stage ring, ONE barrier per chunk) ----------------
// G1: g_h(packed f16) = relu(xh[g_tok] @ W1h + b1)   KTOT=512,  NTOT=2048
// G2: g_y = (g_h @ W2h + b2) * g_w                   KTOT=2048, NTOT=512
template <int KTOT, bool G1>
__global__ void __launch_bounds__(256) k_gemm(const float* __restrict__ bias)
{
    constexpr int NTOT = G1 ? HID : DIM;
    constexpr int CH = KTOT / BKH;

    extern __shared__ __align__(16) char smem[];

    int e = blockIdx.z;
    int seg0 = g_offsets[e], seg1 = g_offsets[e + 1];
    int m0 = seg0 + blockIdx.y * BM;
    if (m0 >= seg1) return;
    int n0 = blockIdx.x * BN;

    const __half* Asrc = G1 ? (const __half*)g_xh : (const __half*)g_h;
    const __half* W    = G1 ? (const __half*)g_W1h : (const __half*)g_W2h;

    int tid = threadIdx.x;
    int lane = tid & 31, wid = tid >> 5;
    int warp_m = wid & 1, warp_n = wid >> 1;

    // ---- cp.async mapping: pieces of 16B; row stride 64B; XOR-16B swizzle by row&3 ----
    int pr = tid >> 2;                   // base row 0..63
    int pc = tid & 3;                    // 16B piece in row
    uint32_t swz = (uint32_t)((pc ^ (pr & 3)) * 16);
    uint32_t sbase = smem_u32(smem);

    const __half* aP[2];
    uint32_t aD[2];
    #pragma unroll
    for (int i = 0; i < 2; i++) {
        int r = pr + i * 64;
        int gm = min(m0 + r, seg1 - 1);
        long long srow = G1 ? (long long)g_tok[gm] : (long long)gm;
        aP[i] = Asrc + srow * KTOT + pc * 8;
        aD[i] = sbase + (uint32_t)r * 64u + swz;
    }
    const __half* bP[4];
    uint32_t bD[4];
    #pragma unroll
    for (int k = 0; k < 4; k++) {
        int r = pr + k * 64;
        bP[k] = W + ((long long)e * NTOT + (n0 + r)) * (long long)KTOT + pc * 8;
        bD[k] = sbase + (uint32_t)A_BYTES + (uint32_t)r * 64u + swz;
    }

    auto load_chunk = [&](int c, int s) {
        uint32_t so = (uint32_t)(s * STAGE_BYTES);
        cp16(aD[0] + so, aP[0] + c * BKH);
        cp16(aD[1] + so, aP[1] + c * BKH);
        #pragma unroll
        for (int k = 0; k < 4; k++) cp16(bD[k] + so, bP[k] + c * BKH);
        asm volatile("cp.async.commit_group;" ::: "memory");
    };

    float acc[4][8][4];
    #pragma unroll
    for (int mi = 0; mi < 4; mi++)
        #pragma unroll
        for (int nj = 0; nj < 8; nj++)
            #pragma unroll
            for (int q = 0; q < 4; q++) acc[mi][nj][q] = 0.0f;

    load_chunk(0, 0);
    load_chunk(1, 1);

    // fragment byte offsets: row&3 == (lane>>2)&3 for all rows a warp touches
    uint32_t fswz = (uint32_t)(((lane & 3) ^ ((lane >> 2) & 3)) * 16);
    uint32_t aOff = (uint32_t)((warp_m * 64 + (lane >> 2)) * 64) + fswz;
    uint32_t bOff = (uint32_t)A_BYTES + (uint32_t)((warp_n * 64 + (lane >> 2)) * 64) + fswz;

    for (int c = 0; c < CH; c++) {
        int s = c & 3;                   // 4-stage ring
        if (c + 1 < CH) asm volatile("cp.async.wait_group 1;" ::: "memory");
        else            asm volatile("cp.async.wait_group 0;" ::: "memory");
        // Single barrier: orders prior-iteration reads of stage (c+2)&3 (chunk c-2)
        // before this iteration's prefetch overwrites it.
        __syncthreads();

        const char* st = smem + s * STAGE_BYTES;

        uint4 aR[8];
        #pragma unroll
        for (int mi = 0; mi < 4; mi++) {
            aR[mi * 2 + 0] = *(const uint4*)(st + aOff + mi * 1024);
            aR[mi * 2 + 1] = *(const uint4*)(st + aOff + mi * 1024 + 512);
        }
        #pragma unroll
        for (int nj = 0; nj < 8; nj++) {
            uint4 b = *(const uint4*)(st + bOff + nj * 512);
            #pragma unroll
            for (int mi = 0; mi < 4; mi++) {
                mma16816(acc[mi][nj],
                         aR[mi * 2].x, aR[mi * 2 + 1].x, aR[mi * 2].y, aR[mi * 2 + 1].y,
                         b.x, b.y);
                mma16816(acc[mi][nj],
                         aR[mi * 2].z, aR[mi * 2 + 1].z, aR[mi * 2].w, aR[mi * 2 + 1].w,
                         b.z, b.w);
            }
        }

        if (c + 2 < CH) load_chunk(c + 2, (c + 2) & 3);
    }

    // ---- epilogue ----
    const float* bias_e = bias + (long long)e * NTOT;
    float2 bv[8];
    #pragma unroll
    for (int nj = 0; nj < 8; nj++) {
        int col = n0 + warp_n * 64 + nj * 8 + (lane & 3) * 2;
        bv[nj] = *(const float2*)(bias_e + col);
    }

    if (G1) {
        __syncthreads();                   // all warps done reading ring before staging reuse
        uint32_t* stg = (uint32_t*)smem;   // [128][132] u32
        #pragma unroll
        for (int mi = 0; mi < 4; mi++) {
            int r0 = warp_m * 64 + mi * 16 + (lane >> 2);   // block-relative row
            #pragma unroll
            for (int nj = 0; nj < 8; nj++) {
                int pos = (warp_n * 2 + (nj >> 2)) * 16 + 4 * (lane & 3) + (nj & 3);
                __half2 h0 = __floats2half2_rn(fmaxf(acc[mi][nj][0] + bv[nj].x, 0.0f),
                                               fmaxf(acc[mi][nj][1] + bv[nj].y, 0.0f));
                __half2 h1 = __floats2half2_rn(fmaxf(acc[mi][nj][2] + bv[nj].x, 0.0f),
                                               fmaxf(acc[mi][nj][3] + bv[nj].y, 0.0f));
                stg[r0 * 132 + pos]       = h2u(h0);
                stg[(r0 + 8) * 132 + pos] = h2u(h1);
            }
        }
        __syncthreads();
        uint32_t* gh = (uint32_t*)g_h;
        #pragma unroll
        for (int it = 0; it < 16; it++) {
            int j = tid + it * 256;            // 4096 uint4 total
            int row = j >> 5, q = j & 31;      // 128 rows x 32 uint4
            if (m0 + row < seg1) {
                uint4 v = *(const uint4*)(stg + row * 132 + q * 4);
                *(uint4*)(gh + (long long)(m0 + row) * (HID / 2) + (n0 >> 1) + q * 4) = v;
            }
        }
    } else {
        #pragma unroll
        for (int mi = 0; mi < 4; mi++) {
            int r0 = m0 + warp_m * 64 + mi * 16 + (lane >> 2);
            int r1 = r0 + 8;
            bool ok0 = r0 < seg1, ok1 = r1 < seg1;
            float w0 = ok0 ? g_w[r0] : 0.0f;
            float w1 = ok1 ? g_w[r1] : 0.0f;
            float* d0 = g_y + (long long)r0 * DIM;
            float* d1 = g_y + (long long)r1 * DIM;
            #pragma unroll
            for (int nj = 0; nj < 8; nj++) {
                int col = n0 + warp_n * 64 + nj * 8 + (lane & 3) * 2;
                float2 v0, v1;
                v0.x = (acc[mi][nj][0] + bv[nj].x) * w0;
                v0.y = (acc[mi][nj][1] + bv[nj].y) * w0;
                v1.x = (acc[mi][nj][2] + bv[nj].x) * w1;
                v1.y = (acc[mi][nj][3] + bv[nj].y) * w1;
                if (ok0) *(float2*)(d0 + col) = v0;
                if (ok1) *(float2*)(d1 + col) = v1;
            }
        }
    }
}

// ---------------- per-token gather ----------------
__global__ void k_gather(float* __restrict__ out) {
    int t = blockIdx.x;
    int c = threadIdx.x;   // 128 threads * float4 = 512 floats
    int cnt = g_cnt[t];
    int p0 = g_pos[2 * t];
    float4 v = ((const float4*)(g_y + (long long)p0 * DIM))[c];
    if (cnt == 2) {
        int p1 = g_pos[2 * t + 1];
        float4 u = ((const float4*)(g_y + (long long)p1 * DIM))[c];
        v.x += u.x; v.y += u.y; v.z += u.z; v.w += u.w;
    }
    ((float4*)(out + (long long)t * DIM))[c] = v;
}

// ---------------- launch ----------------
extern "C" void kernel_launch(void* const* d_in, const int* in_sizes, int n_in,
                              void* d_out, int out_size)
{
    const float* x      = (const float*)d_in[0];
    const int*   assign = (const int*)d_in[1];
    const float* W1     = (const float*)d_in[2];
    const float* b1     = (const float*)d_in[3];
    const float* W2     = (const float*)d_in[4];
    const float* b2     = (const float*)d_in[5];
    float* out = (float*)d_out;

    cudaFuncSetAttribute(k_gemm<DIM, true>,  cudaFuncAttributeMaxDynamicSharedMemorySize, SMEM_BYTES);
    cudaFuncSetAttribute(k_gemm<HID, false>, cudaFuncAttributeMaxDynamicSharedMemorySize, SMEM_BYTES);

    // pre-pack to fp16, k-fragment packed; W transposed to [n][k]; zeroes g_counts
    k_pack_x<<<NTOK, 256>>>(x);
    k_pack_w<<<dim3(64, 16, 16), dim3(32, 8)>>>(W1, W2);

    // routing (block-aggregated atomics; scan fused into k_count)
    k_count<<<NTOK / 256, 256>>>(assign);
    k_place<<<NTOK / 256, 256>>>(assign);

    // GEMM1: entries x 512 @ 512 x 2048 -> g_h (fp16 packed)
    dim3 g1(HID / BN, MAXE / BM, NEXP);   // (8, 512, 8)
    k_gemm<DIM, true><<<g1, 256, SMEM_BYTES>>>(b1);

    // GEMM2: entries x 2048 @ 2048 x 512 -> g_y
    dim3 g2(DIM / BN, MAXE / BM, NEXP);   // (2, 512, 8)
    k_gemm<HID, false><<<g2, 256, SMEM_BYTES>>>(b2);

    k_gather<<<NTOK, 128>>>(out);
}